// round 1
// baseline (speedup 1.0000x reference)
#include <cuda_runtime.h>
#include <cuda_bf16.h>
#include <cstdint>

// Problem constants
#define Bc   8
#define Nn   4096
#define Cc   384
#define Hh   8
#define HD   48
#define KDIM 384          // inner dim of both GEMMs
#define M_ROWS (Bc*Nn)    // 32768
#define QKV_COLS (3*Cc)   // 1152
#define DN 0.3799178428257963f   // 48^-0.25
#define KEPS 1e-3f
#define EPS  1e-8f

// Scratch (device globals; allocation APIs are forbidden)
__device__ float g_qp [Bc*Hh*Nn*HD];   // relu(dn*q)+eps, layout (b,h,n,e)
__device__ float g_kp [Bc*Hh*Nn*HD];   // relu(dn*k)+eps
__device__ float g_v  [Bc*Hh*Nn*HD];   // raw v
__device__ float g_att[Bc*Hh*Nn*HD];   // attention out, (b,h,n,e) contiguous == (B,N,C) flat
__device__ float g_kptv[Bc*Hh*HD*HD];  // per (b,h): 48x48
__device__ float g_ks  [Bc*Hh*HD];     // per (b,h): 48

// ---------------------------------------------------------------------------
// zero kptv / ks accumulators
// ---------------------------------------------------------------------------
__global__ void zero_acc_kernel() {
    int i = blockIdx.x * 256 + threadIdx.x;
    if (i < Bc*Hh*HD*HD) g_kptv[i] = 0.f;
    if (i < Bc*Hh*HD)    g_ks[i]   = 0.f;
}

// ---------------------------------------------------------------------------
// GEMM1: qkv = x @ Wqkv^T with fused feature-map epilogue + scatter
// A: (32768, 384) row-major, W: (1152, 384) row-major
// ---------------------------------------------------------------------------
#define BM 64
#define BN 64
#define BK 16

__global__ __launch_bounds__(256) void gemm_qkv_kernel(
    const float* __restrict__ A, const float* __restrict__ W)
{
    __shared__ float As[BK][BM];
    __shared__ float Bs[BK][BN];

    const int t  = threadIdx.x;
    const int tx = t & 15;
    const int ty = t >> 4;
    const int row0 = blockIdx.x * BM;
    const int col0 = blockIdx.y * BN;

    const int lr = t >> 2;            // 0..63
    const int lk = (t & 3) * 4;       // 0,4,8,12

    const float* Aptr = A + (size_t)(row0 + lr) * KDIM + lk;
    const float* Wptr = W + (size_t)(col0 + lr) * KDIM + lk;

    float acc[4][4];
    #pragma unroll
    for (int i = 0; i < 4; i++)
        #pragma unroll
        for (int j = 0; j < 4; j++) acc[i][j] = 0.f;

    for (int k0 = 0; k0 < KDIM; k0 += BK) {
        float4 av = *(const float4*)(Aptr + k0);
        float4 bv = *(const float4*)(Wptr + k0);
        As[lk+0][lr] = av.x; As[lk+1][lr] = av.y;
        As[lk+2][lr] = av.z; As[lk+3][lr] = av.w;
        Bs[lk+0][lr] = bv.x; Bs[lk+1][lr] = bv.y;
        Bs[lk+2][lr] = bv.z; Bs[lk+3][lr] = bv.w;
        __syncthreads();
        #pragma unroll
        for (int k = 0; k < BK; k++) {
            float4 a = *(const float4*)&As[k][ty*4];
            float4 b = *(const float4*)&Bs[k][tx*4];
            float ar[4] = {a.x, a.y, a.z, a.w};
            float br[4] = {b.x, b.y, b.z, b.w};
            #pragma unroll
            for (int i = 0; i < 4; i++)
                #pragma unroll
                for (int j = 0; j < 4; j++)
                    acc[i][j] += ar[i] * br[j];
        }
        __syncthreads();
    }

    // epilogue: scatter into (b,h,n,e) with feature map for q,k
    #pragma unroll
    for (int i = 0; i < 4; i++) {
        int row = row0 + ty*4 + i;
        int b = row >> 12;
        int n = row & (Nn - 1);
        #pragma unroll
        for (int j = 0; j < 4; j++) {
            int d   = col0 + tx*4 + j;
            int s   = d / Cc;          // 0=q,1=k,2=v
            int rem = d - s * Cc;
            int h   = rem / HD;
            int e   = rem - h * HD;
            float val = acc[i][j];
            size_t off = ((size_t)(b*Hh + h) * Nn + n) * HD + e;
            if (s == 0)      g_qp[off] = fmaxf(val * DN, 0.f) + KEPS;
            else if (s == 1) g_kp[off] = fmaxf(val * DN, 0.f) + KEPS;
            else             g_v[off]  = val;
        }
    }
}

// ---------------------------------------------------------------------------
// K2: per (b,h):  kptv[d][m] = sum_n v[n][d]*kp[n][m];  ks[m] = sum_n kp[n][m]
// grid (64, 16) split-K over n; atomicAdd accumulation
// ---------------------------------------------------------------------------
#define T2 32
#define SPLIT 16
#define ROWS_PER_SPLIT (Nn / SPLIT)   // 256

__global__ __launch_bounds__(256) void kv_agg_kernel()
{
    const int bh    = blockIdx.x;
    const int split = blockIdx.y;
    __shared__ float kps[T2][48];
    __shared__ float vs [T2][48];

    const int t  = threadIdx.x;
    const int dg = t >> 4;   // 0..15 -> d base dg*3
    const int mg = t & 15;   // 0..15 -> m base mg*3

    const size_t base = (size_t)bh * Nn * HD + (size_t)split * ROWS_PER_SPLIT * HD;
    const float* kpb = g_kp + base;
    const float* vb  = g_v  + base;

    float acc[3][3] = {{0.f,0.f,0.f},{0.f,0.f,0.f},{0.f,0.f,0.f}};
    float ksl = 0.f;

    for (int tile = 0; tile < ROWS_PER_SPLIT; tile += T2) {
        for (int idx = t; idx < T2*48; idx += 256) {
            kps[idx/48][idx%48] = kpb[(size_t)tile*HD + idx];
            vs [idx/48][idx%48] = vb [(size_t)tile*HD + idx];
        }
        __syncthreads();
        #pragma unroll 8
        for (int r = 0; r < T2; r++) {
            float vv[3], kk[3];
            #pragma unroll
            for (int a = 0; a < 3; a++) vv[a] = vs[r][dg*3 + a];
            #pragma unroll
            for (int bb = 0; bb < 3; bb++) kk[bb] = kps[r][mg*3 + bb];
            #pragma unroll
            for (int a = 0; a < 3; a++)
                #pragma unroll
                for (int bb = 0; bb < 3; bb++)
                    acc[a][bb] += vv[a] * kk[bb];
        }
        if (t < 48) {
            #pragma unroll 8
            for (int r = 0; r < T2; r++) ksl += kps[r][t];
        }
        __syncthreads();
    }

    #pragma unroll
    for (int a = 0; a < 3; a++)
        #pragma unroll
        for (int bb = 0; bb < 3; bb++)
            atomicAdd(&g_kptv[(size_t)bh*HD*HD + (dg*3 + a)*HD + (mg*3 + bb)], acc[a][bb]);
    if (t < 48) atomicAdd(&g_ks[bh*HD + t], ksl);
}

// ---------------------------------------------------------------------------
// K3: per token:  D = qp . ks ;  att[d] = (qp . kptv[d,:]) / (D + eps)
// grid (64, 32), 128 tokens per block
// ---------------------------------------------------------------------------
#define TOK 128

__global__ __launch_bounds__(256) void attn_out_kernel()
{
    const int bh    = blockIdx.x;
    const int chunk = blockIdx.y;
    __shared__ float kvs[48][49];
    __shared__ float kss[48];
    __shared__ float qs[TOK][49];

    const int t = threadIdx.x;
    for (int idx = t; idx < 48*48; idx += 256)
        kvs[idx/48][idx%48] = g_kptv[(size_t)bh*HD*HD + idx];
    if (t < 48) kss[t] = g_ks[bh*HD + t];

    const size_t qbase = (size_t)bh * Nn * HD + (size_t)chunk * TOK * HD;
    for (int idx = t; idx < TOK*48; idx += 256)
        qs[idx/48][idx%48] = g_qp[qbase + idx];
    __syncthreads();

    const int tg = t >> 3;   // 0..31 -> tokens tg*4..+3
    const int dg = t & 7;    // 0..7  -> d dg*6..+5

    float acc[4][6];
    float Dd[4] = {0.f, 0.f, 0.f, 0.f};
    #pragma unroll
    for (int i = 0; i < 4; i++)
        #pragma unroll
        for (int j = 0; j < 6; j++) acc[i][j] = 0.f;

    #pragma unroll 4
    for (int m = 0; m < 48; m++) {
        float kv[6];
        #pragma unroll
        for (int j = 0; j < 6; j++) kv[j] = kvs[dg*6 + j][m];
        float ksm = kss[m];
        #pragma unroll
        for (int jj = 0; jj < 4; jj++) {
            float q = qs[tg*4 + jj][m];
            Dd[jj] += q * ksm;
            #pragma unroll
            for (int j = 0; j < 6; j++) acc[jj][j] += q * kv[j];
        }
    }

    #pragma unroll
    for (int jj = 0; jj < 4; jj++) {
        float inv = 1.f / (Dd[jj] + EPS);
        size_t obase = ((size_t)bh * Nn + (size_t)chunk * TOK + tg*4 + jj) * HD + dg*6;
        #pragma unroll
        for (int j = 0; j < 6; j++)
            g_att[obase + j] = acc[jj][j] * inv;
    }
}

// ---------------------------------------------------------------------------
// GEMM4: out = att(flat as (32768,384)) @ Wproj^T + bproj
// ---------------------------------------------------------------------------
__global__ __launch_bounds__(256) void gemm_proj_kernel(
    const float* __restrict__ W, const float* __restrict__ bias,
    float* __restrict__ out)
{
    __shared__ float As[BK][BM];
    __shared__ float Bs[BK][BN];

    const int t  = threadIdx.x;
    const int tx = t & 15;
    const int ty = t >> 4;
    const int row0 = blockIdx.x * BM;
    const int col0 = blockIdx.y * BN;

    const int lr = t >> 2;
    const int lk = (t & 3) * 4;

    const float* Aptr = g_att + (size_t)(row0 + lr) * KDIM + lk;
    const float* Wptr = W     + (size_t)(col0 + lr) * KDIM + lk;

    float acc[4][4];
    #pragma unroll
    for (int i = 0; i < 4; i++)
        #pragma unroll
        for (int j = 0; j < 4; j++) acc[i][j] = 0.f;

    for (int k0 = 0; k0 < KDIM; k0 += BK) {
        float4 av = *(const float4*)(Aptr + k0);
        float4 bv = *(const float4*)(Wptr + k0);
        As[lk+0][lr] = av.x; As[lk+1][lr] = av.y;
        As[lk+2][lr] = av.z; As[lk+3][lr] = av.w;
        Bs[lk+0][lr] = bv.x; Bs[lk+1][lr] = bv.y;
        Bs[lk+2][lr] = bv.z; Bs[lk+3][lr] = bv.w;
        __syncthreads();
        #pragma unroll
        for (int k = 0; k < BK; k++) {
            float4 a = *(const float4*)&As[k][ty*4];
            float4 b = *(const float4*)&Bs[k][tx*4];
            float ar[4] = {a.x, a.y, a.z, a.w};
            float br[4] = {b.x, b.y, b.z, b.w};
            #pragma unroll
            for (int i = 0; i < 4; i++)
                #pragma unroll
                for (int j = 0; j < 4; j++)
                    acc[i][j] += ar[i] * br[j];
        }
        __syncthreads();
    }

    #pragma unroll
    for (int i = 0; i < 4; i++) {
        int row = row0 + ty*4 + i;
        #pragma unroll
        for (int j = 0; j < 4; j++) {
            int d = col0 + tx*4 + j;
            out[(size_t)row * Cc + d] = acc[i][j] + bias[d];
        }
    }
}

// ---------------------------------------------------------------------------
extern "C" void kernel_launch(void* const* d_in, const int* in_sizes, int n_in,
                              void* d_out, int out_size)
{
    (void)in_sizes; (void)n_in; (void)out_size;
    const float* x     = (const float*)d_in[0];
    const float* Wqkv  = (const float*)d_in[1];
    const float* Wproj = (const float*)d_in[2];
    const float* bproj = (const float*)d_in[3];
    float* out = (float*)d_out;

    zero_acc_kernel<<<(Bc*Hh*HD*HD + 255) / 256, 256>>>();
    gemm_qkv_kernel<<<dim3(M_ROWS / BM, QKV_COLS / BN), 256>>>(x, Wqkv);
    kv_agg_kernel<<<dim3(Bc*Hh, SPLIT), 256>>>();
    attn_out_kernel<<<dim3(Bc*Hh, Nn / TOK), 256>>>();
    gemm_proj_kernel<<<dim3(M_ROWS / BM, Cc / BN), 256>>>(Wproj, bproj, out);
}

// round 3
// speedup vs baseline: 2.3571x; 2.3571x over previous
#include <cuda_runtime.h>
#include <cuda_bf16.h>
#include <cstdint>

// ---------------------------------------------------------------------------
// Problem constants
// ---------------------------------------------------------------------------
#define Bc   8
#define Nn   4096
#define Cc   384
#define Hh   8
#define HD   48
#define KDIM 384
#define M_ROWS (Bc*Nn)    // 32768
#define QKV_COLS (3*Cc)   // 1152
#define DN 0.3799178428257963f   // 48^-0.25
#define KEPS 1e-3f
#define EPS  1e-8f

// ---------------------------------------------------------------------------
// Scratch (device globals; allocation APIs are forbidden)
// ---------------------------------------------------------------------------
__device__ float g_qp [Bc*Hh*Nn*HD];
__device__ float g_kp [Bc*Hh*Nn*HD];
__device__ float g_v  [Bc*Hh*Nn*HD];
__device__ float g_kptv[Bc*Hh*HD*HD];
__device__ float g_ks  [Bc*Hh*HD];

// bf16 hi/lo split buffers
__device__ __align__(128) __nv_bfloat16 g_xhi [M_ROWS*KDIM];
__device__ __align__(128) __nv_bfloat16 g_xlo [M_ROWS*KDIM];
__device__ __align__(128) __nv_bfloat16 g_wqhi[QKV_COLS*KDIM];
__device__ __align__(128) __nv_bfloat16 g_wqlo[QKV_COLS*KDIM];
__device__ __align__(128) __nv_bfloat16 g_wphi[Cc*KDIM];
__device__ __align__(128) __nv_bfloat16 g_wplo[Cc*KDIM];
__device__ __align__(128) __nv_bfloat16 g_athi[M_ROWS*KDIM];
__device__ __align__(128) __nv_bfloat16 g_atlo[M_ROWS*KDIM];

// ---------------------------------------------------------------------------
// PTX helpers (sm_80-portable: cp.async + ldmatrix + mma.sync)
// ---------------------------------------------------------------------------
__device__ __forceinline__ uint32_t smem_u32(const void* p) {
    uint32_t a;
    asm("{ .reg .u64 t; cvta.to.shared.u64 t, %1; cvt.u32.u64 %0, t; }" : "=r"(a) : "l"(p));
    return a;
}
__device__ __forceinline__ void cp16(uint32_t s, const void* g) {
    asm volatile("cp.async.cg.shared.global [%0], [%1], 16;" :: "r"(s), "l"(g) : "memory");
}
__device__ __forceinline__ void cp_commit() { asm volatile("cp.async.commit_group;" ::: "memory"); }
template <int N> __device__ __forceinline__ void cp_wait() {
    asm volatile("cp.async.wait_group %0;" :: "n"(N) : "memory");
}
#define LDSM4(r, a) \
    asm volatile("ldmatrix.sync.aligned.m8n8.x4.shared.b16 {%0,%1,%2,%3}, [%4];" \
        : "=r"((r)[0]), "=r"((r)[1]), "=r"((r)[2]), "=r"((r)[3]) : "r"(a))

__device__ __forceinline__ void mma16816(float* c, const uint32_t* a, const uint32_t* b) {
    asm volatile(
        "mma.sync.aligned.m16n8k16.row.col.f32.bf16.bf16.f32 "
        "{%0,%1,%2,%3}, {%4,%5,%6,%7}, {%8,%9}, {%0,%1,%2,%3};"
        : "+f"(c[0]), "+f"(c[1]), "+f"(c[2]), "+f"(c[3])
        : "r"(a[0]), "r"(a[1]), "r"(a[2]), "r"(a[3]), "r"(b[0]), "r"(b[1]));
}

// ---------------------------------------------------------------------------
// split fp32 -> bf16 hi + bf16 lo
// ---------------------------------------------------------------------------
__global__ void split_kernel(const float* __restrict__ src,
                             __nv_bfloat16* __restrict__ hi,
                             __nv_bfloat16* __restrict__ lo, int n4) {
    int i = blockIdx.x * 256 + threadIdx.x;
    if (i >= n4) return;
    float4 v = ((const float4*)src)[i];
    __nv_bfloat16 h0 = __float2bfloat16(v.x), h1 = __float2bfloat16(v.y);
    __nv_bfloat16 h2 = __float2bfloat16(v.z), h3 = __float2bfloat16(v.w);
    __nv_bfloat16 l0 = __float2bfloat16(v.x - __bfloat162float(h0));
    __nv_bfloat16 l1 = __float2bfloat16(v.y - __bfloat162float(h1));
    __nv_bfloat16 l2 = __float2bfloat16(v.z - __bfloat162float(h2));
    __nv_bfloat16 l3 = __float2bfloat16(v.w - __bfloat162float(h3));
    ((__nv_bfloat162*)hi)[i*2]   = __nv_bfloat162(h0, h1);
    ((__nv_bfloat162*)hi)[i*2+1] = __nv_bfloat162(h2, h3);
    ((__nv_bfloat162*)lo)[i*2]   = __nv_bfloat162(l0, l1);
    ((__nv_bfloat162*)lo)[i*2+1] = __nv_bfloat162(l2, l3);
}

__global__ void zero_acc_kernel() {
    int i = blockIdx.x * 256 + threadIdx.x;
    if (i < Bc*Hh*HD*HD) g_kptv[i] = 0.f;
    if (i < Bc*Hh*HD)    g_ks[i]   = 0.f;
}

// ---------------------------------------------------------------------------
// Split-bf16 tensor-core GEMM via mma.sync.
// C(M_ROWS x cols) = A(M_ROWS x 384) @ W(cols x 384)^T
// CTA tile 128(M) x 192(N); 8 warps, warp tile 64x48.
// K chunks of 32; 3-stage cp.async pipeline.
// Rows in smem padded to 40 bf16 (80B) -> conflict-free ldmatrix.
// MODE 0: QKV feature-map epilogue + scatter; MODE 1: out = acc + bias.
// ---------------------------------------------------------------------------
#define KC 32
#define A_ROW_B 80            // bytes per smem row (40 bf16)
#define OFF_ALO 10240         // 128*80
#define OFF_WHI 20480
#define OFF_WLO 35840         // 20480 + 192*80
#define STG     51200         // 35840 + 192*80
#define NSTG 3
#define SMEM_TOTAL (NSTG*STG) // 153600

template <int MODE>
__global__ __launch_bounds__(256) void gemm_mma(
    const __nv_bfloat16* __restrict__ Ahi, const __nv_bfloat16* __restrict__ Alo,
    const __nv_bfloat16* __restrict__ Whi, const __nv_bfloat16* __restrict__ Wlo,
    const float* __restrict__ bias, float* __restrict__ out)
{
    extern __shared__ char smem[];
    const uint32_t sb = smem_u32(smem);
    const int tid = threadIdx.x;
    const int wid = tid >> 5;
    const int l   = tid & 31;
    const int wm  = wid & 1;      // 2 M-blocks of 64
    const int wn  = wid >> 1;     // 4 N-blocks of 48
    const int row0 = blockIdx.x * 128;
    const int col0 = blockIdx.y * 192;

    // ---- loader for chunk L (k = L*32..+31) into stage s ----
    auto load_chunk = [&](int L, int s) {
        const uint32_t st = sb + s * STG;
        const int kof = L * KC;
        #pragma unroll
        for (int i = 0; i < 2; i++) {            // A: 128 rows x 4 segs
            int idx = tid + i * 256;
            int row = idx >> 2, seg = idx & 3;
            uint32_t dof = (uint32_t)(row * A_ROW_B + seg * 16);
            const size_t gof = (size_t)(row0 + row) * KDIM + kof + seg * 8;
            cp16(st + dof,           Ahi + gof);
            cp16(st + OFF_ALO + dof, Alo + gof);
        }
        #pragma unroll
        for (int i = 0; i < 3; i++) {            // W: 192 rows x 4 segs
            int idx = tid + i * 256;
            int row = idx >> 2, seg = idx & 3;
            uint32_t dof = (uint32_t)(row * A_ROW_B + seg * 16);
            const size_t gof = (size_t)(col0 + row) * KDIM + kof + seg * 8;
            cp16(st + OFF_WHI + dof, Whi + gof);
            cp16(st + OFF_WLO + dof, Wlo + gof);
        }
        cp_commit();
    };

    // per-thread ldmatrix lane offsets (bytes, within a region)
    const uint32_t a_base = (uint32_t)(((wm*64 + (l & 15)) * 40 + (l >> 4) * 8) * 2);
    const uint32_t b_base = (uint32_t)(((wn*48 + ((l >> 4) & 1) * 8 + (l & 7)) * 40
                                        + ((l >> 3) & 1) * 8) * 2);

    float acc[4][6][4];
    #pragma unroll
    for (int mt = 0; mt < 4; mt++)
        #pragma unroll
        for (int nt = 0; nt < 6; nt++)
            #pragma unroll
            for (int r = 0; r < 4; r++) acc[mt][nt][r] = 0.f;

    load_chunk(0, 0);
    load_chunk(1, 1);
    load_chunk(2, 2);

    #pragma unroll 1
    for (int c = 0; c < KDIM / KC; c++) {
        cp_wait<2>();
        __syncthreads();
        const uint32_t st = sb + (c % 3) * STG;

        #pragma unroll
        for (int ks = 0; ks < 2; ks++) {
            const uint32_t ko = ks * 32;     // 16 cols * 2B
            uint32_t ah[4][4], al[4][4], bh[3][4], bl[3][4];
            #pragma unroll
            for (int mt = 0; mt < 4; mt++) {
                LDSM4(ah[mt], st + a_base + mt*1280 + ko);
                LDSM4(al[mt], st + OFF_ALO + a_base + mt*1280 + ko);
            }
            #pragma unroll
            for (int np = 0; np < 3; np++) {
                LDSM4(bh[np], st + OFF_WHI + b_base + np*1280 + ko);
                LDSM4(bl[np], st + OFF_WLO + b_base + np*1280 + ko);
            }
            #pragma unroll
            for (int mt = 0; mt < 4; mt++)
                #pragma unroll
                for (int np = 0; np < 3; np++)
                    #pragma unroll
                    for (int hf = 0; hf < 2; hf++) {
                        float* C = acc[mt][np*2 + hf];
                        mma16816(C, ah[mt], &bh[np][hf*2]);
                        mma16816(C, ah[mt], &bl[np][hf*2]);
                        mma16816(C, al[mt], &bh[np][hf*2]);
                    }
        }
        __syncthreads();
        if (c + 3 < KDIM / KC) load_chunk(c + 3, c % 3);
    }

    // ---- epilogue: accums -> smem [128][200] -> global ----
    float* epi = (float*)smem;
    const int g   = l >> 2;
    const int tig = l & 3;
    #pragma unroll
    for (int mt = 0; mt < 4; mt++)
        #pragma unroll
        for (int nt = 0; nt < 6; nt++) {
            int row = wm*64 + mt*16 + g;
            int col = wn*48 + nt*8 + 2*tig;
            *(float2*)&epi[row * 200 + col]       = make_float2(acc[mt][nt][0], acc[mt][nt][1]);
            *(float2*)&epi[(row + 8) * 200 + col] = make_float2(acc[mt][nt][2], acc[mt][nt][3]);
        }
    __syncthreads();

    if (MODE == 0) {
        const int b  = row0 >> 12;
        const int n0 = row0 & (Nn - 1);
        #pragma unroll
        for (int g4 = 0; g4 < 4; g4++) {
            const int gg = blockIdx.y * 4 + g4;
            const int sI = gg >> 3;        // 0=q,1=k,2=v
            const int h  = gg & 7;
            float* P = (sI == 0 ? g_qp : (sI == 1 ? g_kp : g_v))
                       + ((size_t)(b * Hh + h) * Nn + n0) * HD;
            #pragma unroll 8
            for (int it = 0; it < 24; it++) {
                int idx = tid + it * 256;
                int m = idx / 48, e = idx - m * 48;
                float v = epi[m * 200 + g4 * 48 + e];
                if (sI < 2) v = fmaxf(v * DN, 0.f) + KEPS;
                P[idx] = v;
            }
        }
    } else {
        #pragma unroll 8
        for (int it = 0; it < 96; it++) {
            int idx = tid + it * 256;
            int m = idx / 192, j = idx - m * 192;
            out[(size_t)(row0 + m) * Cc + col0 + j] = epi[m * 200 + j] + bias[col0 + j];
        }
    }
}

// ---------------------------------------------------------------------------
// K2: per (b,h): kptv[d][m] = sum_n v[n][d]*kp[n][m]; ks[m] = sum_n kp[n][m]
// ---------------------------------------------------------------------------
#define T2 32
#define SPLIT 16
#define ROWS_PER_SPLIT (Nn / SPLIT)

__global__ __launch_bounds__(256) void kv_agg_kernel()
{
    const int bh    = blockIdx.x;
    const int split = blockIdx.y;
    __shared__ float kps[T2][48];
    __shared__ float vs [T2][48];

    const int t  = threadIdx.x;
    const int dg = t >> 4;
    const int mg = t & 15;

    const size_t base = (size_t)bh * Nn * HD + (size_t)split * ROWS_PER_SPLIT * HD;
    const float* kpb = g_kp + base;
    const float* vb  = g_v  + base;

    float acc[3][3] = {{0.f,0.f,0.f},{0.f,0.f,0.f},{0.f,0.f,0.f}};
    float ksl = 0.f;

    for (int tile = 0; tile < ROWS_PER_SPLIT; tile += T2) {
        for (int idx = t; idx < T2*48; idx += 256) {
            kps[idx/48][idx%48] = kpb[(size_t)tile*HD + idx];
            vs [idx/48][idx%48] = vb [(size_t)tile*HD + idx];
        }
        __syncthreads();
        #pragma unroll 8
        for (int r = 0; r < T2; r++) {
            float vv[3], kk[3];
            #pragma unroll
            for (int a = 0; a < 3; a++) vv[a] = vs[r][dg*3 + a];
            #pragma unroll
            for (int bb = 0; bb < 3; bb++) kk[bb] = kps[r][mg*3 + bb];
            #pragma unroll
            for (int a = 0; a < 3; a++)
                #pragma unroll
                for (int bb = 0; bb < 3; bb++)
                    acc[a][bb] += vv[a] * kk[bb];
        }
        if (t < 48) {
            #pragma unroll 8
            for (int r = 0; r < T2; r++) ksl += kps[r][t];
        }
        __syncthreads();
    }

    #pragma unroll
    for (int a = 0; a < 3; a++)
        #pragma unroll
        for (int bb = 0; bb < 3; bb++)
            atomicAdd(&g_kptv[(size_t)bh*HD*HD + (dg*3 + a)*HD + (mg*3 + bb)], acc[a][bb]);
    if (t < 48) atomicAdd(&g_ks[bh*HD + t], ksl);
}

// ---------------------------------------------------------------------------
// K3: per token: D = qp.ks; att[d] = (qp . kptv[d,:]) / (D + eps)
// writes bf16 hi/lo split directly (feeds GEMM4)
// ---------------------------------------------------------------------------
#define TOK 128

__global__ __launch_bounds__(256) void attn_out_kernel()
{
    const int bh    = blockIdx.x;
    const int chunk = blockIdx.y;
    __shared__ float kvs[48][49];
    __shared__ float kss[48];
    __shared__ float qs[TOK][49];

    const int t = threadIdx.x;
    for (int idx = t; idx < 48*48; idx += 256)
        kvs[idx/48][idx%48] = g_kptv[(size_t)bh*HD*HD + idx];
    if (t < 48) kss[t] = g_ks[bh*HD + t];

    const size_t qbase = (size_t)bh * Nn * HD + (size_t)chunk * TOK * HD;
    for (int idx = t; idx < TOK*48; idx += 256)
        qs[idx/48][idx%48] = g_qp[qbase + idx];
    __syncthreads();

    const int tg = t >> 3;
    const int dg = t & 7;

    float acc[4][6];
    float Dd[4] = {0.f, 0.f, 0.f, 0.f};
    #pragma unroll
    for (int i = 0; i < 4; i++)
        #pragma unroll
        for (int j = 0; j < 6; j++) acc[i][j] = 0.f;

    #pragma unroll 4
    for (int m = 0; m < 48; m++) {
        float kv[6];
        #pragma unroll
        for (int j = 0; j < 6; j++) kv[j] = kvs[dg*6 + j][m];
        float ksm = kss[m];
        #pragma unroll
        for (int jj = 0; jj < 4; jj++) {
            float q = qs[tg*4 + jj][m];
            Dd[jj] += q * ksm;
            #pragma unroll
            for (int j = 0; j < 6; j++) acc[jj][j] += q * kv[j];
        }
    }

    #pragma unroll
    for (int jj = 0; jj < 4; jj++) {
        float inv = 1.f / (Dd[jj] + EPS);
        size_t obase = ((size_t)bh * Nn + (size_t)chunk * TOK + tg*4 + jj) * HD + dg*6;
        #pragma unroll
        for (int j = 0; j < 6; j++) {
            float v = acc[jj][j] * inv;
            __nv_bfloat16 h = __float2bfloat16(v);
            g_athi[obase + j] = h;
            g_atlo[obase + j] = __float2bfloat16(v - __bfloat162float(h));
        }
    }
}

// ---------------------------------------------------------------------------
extern "C" void kernel_launch(void* const* d_in, const int* in_sizes, int n_in,
                              void* d_out, int out_size)
{
    (void)in_sizes; (void)n_in; (void)out_size;
    const float* x     = (const float*)d_in[0];
    const float* Wqkv  = (const float*)d_in[1];
    const float* Wproj = (const float*)d_in[2];
    const float* bproj = (const float*)d_in[3];
    float* out = (float*)d_out;

    cudaFuncSetAttribute(gemm_mma<0>, cudaFuncAttributeMaxDynamicSharedMemorySize, SMEM_TOTAL);
    cudaFuncSetAttribute(gemm_mma<1>, cudaFuncAttributeMaxDynamicSharedMemorySize, SMEM_TOTAL);

    __nv_bfloat16 *xhi, *xlo, *wqhi, *wqlo, *wphi, *wplo, *athi, *atlo;
    cudaGetSymbolAddress((void**)&xhi,  g_xhi);
    cudaGetSymbolAddress((void**)&xlo,  g_xlo);
    cudaGetSymbolAddress((void**)&wqhi, g_wqhi);
    cudaGetSymbolAddress((void**)&wqlo, g_wqlo);
    cudaGetSymbolAddress((void**)&wphi, g_wphi);
    cudaGetSymbolAddress((void**)&wplo, g_wplo);
    cudaGetSymbolAddress((void**)&athi, g_athi);
    cudaGetSymbolAddress((void**)&atlo, g_atlo);

    split_kernel<<<(M_ROWS*KDIM/4 + 255)/256, 256>>>(x, xhi, xlo, M_ROWS*KDIM/4);
    split_kernel<<<(QKV_COLS*KDIM/4 + 255)/256, 256>>>(Wqkv, wqhi, wqlo, QKV_COLS*KDIM/4);
    split_kernel<<<(Cc*KDIM/4 + 255)/256, 256>>>(Wproj, wphi, wplo, Cc*KDIM/4);
    zero_acc_kernel<<<(Bc*Hh*HD*HD + 255)/256, 256>>>();

    gemm_mma<0><<<dim3(M_ROWS/128, QKV_COLS/192), 256, SMEM_TOTAL>>>(
        xhi, xlo, wqhi, wqlo, nullptr, nullptr);

    kv_agg_kernel<<<dim3(Bc*Hh, SPLIT), 256>>>();
    attn_out_kernel<<<dim3(Bc*Hh, Nn/TOK), 256>>>();

    gemm_mma<1><<<dim3(M_ROWS/128, Cc/192), 256, SMEM_TOTAL>>>(
        athi, atlo, wphi, wplo, bproj, out);
}

// round 4
// speedup vs baseline: 3.2502x; 1.3789x over previous
#include <cuda_runtime.h>
#include <cuda_fp16.h>
#include <cstdint>

// ---------------------------------------------------------------------------
// Problem constants
// ---------------------------------------------------------------------------
#define Bc   8
#define Nn   4096
#define Cc   384
#define Hh   8
#define HD   48
#define KDIM 384
#define M_ROWS (Bc*Nn)    // 32768
#define QKV_COLS (3*Cc)   // 1152
#define DN 0.3799178428257963f   // 48^-0.25
#define KEPS 1e-3f
#define EPS  1e-8f

// ---------------------------------------------------------------------------
// Scratch (device globals; allocation APIs are forbidden)
// ---------------------------------------------------------------------------
__device__ float g_qp [Bc*Hh*Nn*HD];
__device__ float g_kp [Bc*Hh*Nn*HD];
__device__ float g_v  [Bc*Hh*Nn*HD];
__device__ float g_kptv[Bc*Hh*HD*HD];
__device__ float g_ks  [Bc*Hh*HD];

// fp16 operand buffers (A split hi/lo; W single)
__device__ __align__(128) __half g_xhi [M_ROWS*KDIM];
__device__ __align__(128) __half g_xlo [M_ROWS*KDIM];
__device__ __align__(128) __half g_wq  [QKV_COLS*KDIM];
__device__ __align__(128) __half g_wp  [Cc*KDIM];
__device__ __align__(128) __half g_athi[M_ROWS*KDIM];
__device__ __align__(128) __half g_atlo[M_ROWS*KDIM];

// ---------------------------------------------------------------------------
// PTX helpers (sm_80-portable: cp.async + ldmatrix + mma.sync)
// ---------------------------------------------------------------------------
__device__ __forceinline__ uint32_t smem_u32(const void* p) {
    uint32_t a;
    asm("{ .reg .u64 t; cvta.to.shared.u64 t, %1; cvt.u32.u64 %0, t; }" : "=r"(a) : "l"(p));
    return a;
}
__device__ __forceinline__ void cp16(uint32_t s, const void* g) {
    asm volatile("cp.async.cg.shared.global [%0], [%1], 16;" :: "r"(s), "l"(g) : "memory");
}
__device__ __forceinline__ void cp_commit() { asm volatile("cp.async.commit_group;" ::: "memory"); }
template <int N> __device__ __forceinline__ void cp_wait() {
    asm volatile("cp.async.wait_group %0;" :: "n"(N) : "memory");
}
#define LDSM4(r, a) \
    asm volatile("ldmatrix.sync.aligned.m8n8.x4.shared.b16 {%0,%1,%2,%3}, [%4];" \
        : "=r"((r)[0]), "=r"((r)[1]), "=r"((r)[2]), "=r"((r)[3]) : "r"(a))

__device__ __forceinline__ void mma16816(float* c, const uint32_t* a, const uint32_t* b) {
    asm volatile(
        "mma.sync.aligned.m16n8k16.row.col.f32.f16.f16.f32 "
        "{%0,%1,%2,%3}, {%4,%5,%6,%7}, {%8,%9}, {%0,%1,%2,%3};"
        : "+f"(c[0]), "+f"(c[1]), "+f"(c[2]), "+f"(c[3])
        : "r"(a[0]), "r"(a[1]), "r"(a[2]), "r"(a[3]), "r"(b[0]), "r"(b[1]));
}

// ---------------------------------------------------------------------------
// prep kernels
// ---------------------------------------------------------------------------
__global__ void split_x_kernel(const float* __restrict__ src,
                               __half* __restrict__ hi,
                               __half* __restrict__ lo, int n4) {
    int i = blockIdx.x * 256 + threadIdx.x;
    if (i >= n4) return;
    float4 v = ((const float4*)src)[i];
    __half h0 = __float2half(v.x), h1 = __float2half(v.y);
    __half h2 = __float2half(v.z), h3 = __float2half(v.w);
    __half l0 = __float2half(v.x - __half2float(h0));
    __half l1 = __float2half(v.y - __half2float(h1));
    __half l2 = __float2half(v.z - __half2float(h2));
    __half l3 = __float2half(v.w - __half2float(h3));
    ((__half2*)hi)[i*2]   = __half2(h0, h1);
    ((__half2*)hi)[i*2+1] = __half2(h2, h3);
    ((__half2*)lo)[i*2]   = __half2(l0, l1);
    ((__half2*)lo)[i*2+1] = __half2(l2, l3);
}

// convert both weight matrices to fp16 and zero the kv accumulators
__global__ void prep_w_kernel(const float* __restrict__ Wqkv,
                              const float* __restrict__ Wproj) {
    int i = blockIdx.x * 256 + threadIdx.x;
    if (i < QKV_COLS*KDIM) g_wq[i] = __float2half(Wqkv[i]);
    if (i < Cc*KDIM)       g_wp[i] = __float2half(Wproj[i]);
    if (i < Bc*Hh*HD*HD)   g_kptv[i] = 0.f;
    if (i < Bc*Hh*HD)      g_ks[i]   = 0.f;
}

// ---------------------------------------------------------------------------
// 2-term split-fp16 tensor-core GEMM via mma.sync.
// C = (A_hi + A_lo)(M_ROWS x 384) @ W(cols x 384)^T
// CTA tile 128(M) x 192(N); 8 warps, warp tile 64x48.
// K chunks of 32; 3-stage cp.async pipeline. Rows padded to 40 halfs (80B).
// MODE 0: QKV feature-map epilogue + scatter; MODE 1: out = acc + bias.
// ---------------------------------------------------------------------------
#define KC 32
#define A_ROW_B 80
#define OFF_ALO 10240         // 128*80
#define OFF_W   20480
#define STG     35840         // 20480 + 192*80
#define NSTG 3
#define SMEM_TOTAL (NSTG*STG) // 107520  (epilogue reuse: 128*200*4 = 102400)

template <int MODE>
__global__ __launch_bounds__(256) void gemm_mma(
    const __half* __restrict__ Ahi, const __half* __restrict__ Alo,
    const __half* __restrict__ W,
    const float* __restrict__ bias, float* __restrict__ out)
{
    extern __shared__ char smem[];
    const uint32_t sb = smem_u32(smem);
    const int tid = threadIdx.x;
    const int wid = tid >> 5;
    const int l   = tid & 31;
    const int wm  = wid & 1;      // 2 M-blocks of 64
    const int wn  = wid >> 1;     // 4 N-blocks of 48
    const int row0 = blockIdx.x * 128;
    const int col0 = blockIdx.y * 192;

    auto load_chunk = [&](int L, int s) {
        const uint32_t st = sb + s * STG;
        const int kof = L * KC;
        #pragma unroll
        for (int i = 0; i < 2; i++) {            // A: 128 rows x 4 segs, hi+lo
            int idx = tid + i * 256;
            int row = idx >> 2, seg = idx & 3;
            uint32_t dof = (uint32_t)(row * A_ROW_B + seg * 16);
            const size_t gof = (size_t)(row0 + row) * KDIM + kof + seg * 8;
            cp16(st + dof,           Ahi + gof);
            cp16(st + OFF_ALO + dof, Alo + gof);
        }
        #pragma unroll
        for (int i = 0; i < 3; i++) {            // W: 192 rows x 4 segs
            int idx = tid + i * 256;
            int row = idx >> 2, seg = idx & 3;
            uint32_t dof = (uint32_t)(row * A_ROW_B + seg * 16);
            cp16(st + OFF_W + dof, W + (size_t)(col0 + row) * KDIM + kof + seg * 8);
        }
        cp_commit();
    };

    const uint32_t a_base = (uint32_t)(((wm*64 + (l & 15)) * 40 + (l >> 4) * 8) * 2);
    const uint32_t b_base = (uint32_t)(((wn*48 + ((l >> 4) & 1) * 8 + (l & 7)) * 40
                                        + ((l >> 3) & 1) * 8) * 2);

    float acc[4][6][4];
    #pragma unroll
    for (int mt = 0; mt < 4; mt++)
        #pragma unroll
        for (int nt = 0; nt < 6; nt++)
            #pragma unroll
            for (int r = 0; r < 4; r++) acc[mt][nt][r] = 0.f;

    load_chunk(0, 0);
    load_chunk(1, 1);
    load_chunk(2, 2);

    #pragma unroll 1
    for (int c = 0; c < KDIM / KC; c++) {
        cp_wait<2>();
        __syncthreads();
        const uint32_t st = sb + (c % 3) * STG;

        #pragma unroll
        for (int ks = 0; ks < 2; ks++) {
            const uint32_t ko = ks * 32;     // 16 cols * 2B
            uint32_t ah[4][4], al[4][4], bh[3][4];
            #pragma unroll
            for (int np = 0; np < 3; np++)
                LDSM4(bh[np], st + OFF_W + b_base + np*1280 + ko);
            #pragma unroll
            for (int mt = 0; mt < 4; mt++)
                LDSM4(ah[mt], st + a_base + mt*1280 + ko);
            #pragma unroll
            for (int mt = 0; mt < 4; mt++)
                #pragma unroll
                for (int np = 0; np < 3; np++)
                    #pragma unroll
                    for (int hf = 0; hf < 2; hf++)
                        mma16816(acc[mt][np*2 + hf], ah[mt], &bh[np][hf*2]);
            #pragma unroll
            for (int mt = 0; mt < 4; mt++)
                LDSM4(al[mt], st + OFF_ALO + a_base + mt*1280 + ko);
            #pragma unroll
            for (int mt = 0; mt < 4; mt++)
                #pragma unroll
                for (int np = 0; np < 3; np++)
                    #pragma unroll
                    for (int hf = 0; hf < 2; hf++)
                        mma16816(acc[mt][np*2 + hf], al[mt], &bh[np][hf*2]);
        }
        __syncthreads();
        if (c + 3 < KDIM / KC) load_chunk(c + 3, c % 3);
    }

    // ---- epilogue: accums -> smem [128][200] -> global ----
    float* epi = (float*)smem;
    const int g   = l >> 2;
    const int tig = l & 3;
    #pragma unroll
    for (int mt = 0; mt < 4; mt++)
        #pragma unroll
        for (int nt = 0; nt < 6; nt++) {
            int row = wm*64 + mt*16 + g;
            int col = wn*48 + nt*8 + 2*tig;
            *(float2*)&epi[row * 200 + col]       = make_float2(acc[mt][nt][0], acc[mt][nt][1]);
            *(float2*)&epi[(row + 8) * 200 + col] = make_float2(acc[mt][nt][2], acc[mt][nt][3]);
        }
    __syncthreads();

    if (MODE == 0) {
        const int b  = row0 >> 12;
        const int n0 = row0 & (Nn - 1);
        #pragma unroll
        for (int g4 = 0; g4 < 4; g4++) {
            const int gg = blockIdx.y * 4 + g4;
            const int sI = gg >> 3;        // 0=q,1=k,2=v
            const int h  = gg & 7;
            float* P = (sI == 0 ? g_qp : (sI == 1 ? g_kp : g_v))
                       + ((size_t)(b * Hh + h) * Nn + n0) * HD;
            #pragma unroll 8
            for (int it = 0; it < 24; it++) {
                int idx = tid + it * 256;
                int m = idx / 48, e = idx - m * 48;
                float v = epi[m * 200 + g4 * 48 + e];
                if (sI < 2) v = fmaxf(v * DN, 0.f) + KEPS;
                P[idx] = v;
            }
        }
    } else {
        #pragma unroll 8
        for (int it = 0; it < 96; it++) {
            int idx = tid + it * 256;
            int m = idx / 192, j = idx - m * 192;
            out[(size_t)(row0 + m) * Cc + col0 + j] = epi[m * 200 + j] + bias[col0 + j];
        }
    }
}

// ---------------------------------------------------------------------------
// K2: per (b,h): kptv[d][m] = sum_n v[n][d]*kp[n][m]; ks[m] = sum_n kp[n][m]
// ---------------------------------------------------------------------------
#define T2 32
#define SPLIT 16
#define ROWS_PER_SPLIT (Nn / SPLIT)

__global__ __launch_bounds__(256) void kv_agg_kernel()
{
    const int bh    = blockIdx.x;
    const int split = blockIdx.y;
    __shared__ float kps[T2][48];
    __shared__ float vs [T2][48];

    const int t  = threadIdx.x;
    const int dg = t >> 4;
    const int mg = t & 15;

    const size_t base = (size_t)bh * Nn * HD + (size_t)split * ROWS_PER_SPLIT * HD;
    const float* kpb = g_kp + base;
    const float* vb  = g_v  + base;

    float acc[3][3] = {{0.f,0.f,0.f},{0.f,0.f,0.f},{0.f,0.f,0.f}};
    float ksl = 0.f;

    for (int tile = 0; tile < ROWS_PER_SPLIT; tile += T2) {
        for (int idx = t; idx < T2*48; idx += 256) {
            kps[idx/48][idx%48] = kpb[(size_t)tile*HD + idx];
            vs [idx/48][idx%48] = vb [(size_t)tile*HD + idx];
        }
        __syncthreads();
        #pragma unroll 8
        for (int r = 0; r < T2; r++) {
            float vv[3], kk[3];
            #pragma unroll
            for (int a = 0; a < 3; a++) vv[a] = vs[r][dg*3 + a];
            #pragma unroll
            for (int bb = 0; bb < 3; bb++) kk[bb] = kps[r][mg*3 + bb];
            #pragma unroll
            for (int a = 0; a < 3; a++)
                #pragma unroll
                for (int bb = 0; bb < 3; bb++)
                    acc[a][bb] += vv[a] * kk[bb];
        }
        if (t < 48) {
            #pragma unroll 8
            for (int r = 0; r < T2; r++) ksl += kps[r][t];
        }
        __syncthreads();
    }

    #pragma unroll
    for (int a = 0; a < 3; a++)
        #pragma unroll
        for (int bb = 0; bb < 3; bb++)
            atomicAdd(&g_kptv[(size_t)bh*HD*HD + (dg*3 + a)*HD + (mg*3 + bb)], acc[a][bb]);
    if (t < 48) atomicAdd(&g_ks[bh*HD + t], ksl);
}

// ---------------------------------------------------------------------------
// K3: per token: D = qp.ks; att[d] = (qp . kptv[d,:]) / (D + eps)
// writes fp16 hi/lo split directly (feeds GEMM4)
// ---------------------------------------------------------------------------
#define TOK 128

__global__ __launch_bounds__(256) void attn_out_kernel()
{
    const int bh    = blockIdx.x;
    const int chunk = blockIdx.y;
    __shared__ float kvs[48][49];
    __shared__ float kss[48];
    __shared__ float qs[TOK][49];

    const int t = threadIdx.x;
    for (int idx = t; idx < 48*48; idx += 256)
        kvs[idx/48][idx%48] = g_kptv[(size_t)bh*HD*HD + idx];
    if (t < 48) kss[t] = g_ks[bh*HD + t];

    const size_t qbase = (size_t)bh * Nn * HD + (size_t)chunk * TOK * HD;
    for (int idx = t; idx < TOK*48; idx += 256)
        qs[idx/48][idx%48] = g_qp[qbase + idx];
    __syncthreads();

    const int tg = t >> 3;
    const int dg = t & 7;

    float acc[4][6];
    float Dd[4] = {0.f, 0.f, 0.f, 0.f};
    #pragma unroll
    for (int i = 0; i < 4; i++)
        #pragma unroll
        for (int j = 0; j < 6; j++) acc[i][j] = 0.f;

    #pragma unroll 4
    for (int m = 0; m < 48; m++) {
        float kv[6];
        #pragma unroll
        for (int j = 0; j < 6; j++) kv[j] = kvs[dg*6 + j][m];
        float ksm = kss[m];
        #pragma unroll
        for (int jj = 0; jj < 4; jj++) {
            float q = qs[tg*4 + jj][m];
            Dd[jj] += q * ksm;
            #pragma unroll
            for (int j = 0; j < 6; j++) acc[jj][j] += q * kv[j];
        }
    }

    #pragma unroll
    for (int jj = 0; jj < 4; jj++) {
        float inv = 1.f / (Dd[jj] + EPS);
        size_t obase = ((size_t)bh * Nn + (size_t)chunk * TOK + tg*4 + jj) * HD + dg*6;
        #pragma unroll
        for (int j = 0; j < 6; j++) {
            float v = acc[jj][j] * inv;
            __half h = __float2half(v);
            g_athi[obase + j] = h;
            g_atlo[obase + j] = __float2half(v - __half2float(h));
        }
    }
}

// ---------------------------------------------------------------------------
extern "C" void kernel_launch(void* const* d_in, const int* in_sizes, int n_in,
                              void* d_out, int out_size)
{
    (void)in_sizes; (void)n_in; (void)out_size;
    const float* x     = (const float*)d_in[0];
    const float* Wqkv  = (const float*)d_in[1];
    const float* Wproj = (const float*)d_in[2];
    const float* bproj = (const float*)d_in[3];
    float* out = (float*)d_out;

    cudaFuncSetAttribute(gemm_mma<0>, cudaFuncAttributeMaxDynamicSharedMemorySize, SMEM_TOTAL);
    cudaFuncSetAttribute(gemm_mma<1>, cudaFuncAttributeMaxDynamicSharedMemorySize, SMEM_TOTAL);

    __half *xhi, *xlo, *wq, *wp, *athi, *atlo;
    cudaGetSymbolAddress((void**)&xhi,  g_xhi);
    cudaGetSymbolAddress((void**)&xlo,  g_xlo);
    cudaGetSymbolAddress((void**)&wq,   g_wq);
    cudaGetSymbolAddress((void**)&wp,   g_wp);
    cudaGetSymbolAddress((void**)&athi, g_athi);
    cudaGetSymbolAddress((void**)&atlo, g_atlo);

    split_x_kernel<<<(M_ROWS*KDIM/4 + 255)/256, 256>>>(x, xhi, xlo, M_ROWS*KDIM/4);
    prep_w_kernel<<<(QKV_COLS*KDIM + 255)/256, 256>>>(Wqkv, Wproj);

    gemm_mma<0><<<dim3(M_ROWS/128, QKV_COLS/192), 256, SMEM_TOTAL>>>(
        xhi, xlo, wq, nullptr, nullptr);

    kv_agg_kernel<<<dim3(Bc*Hh, SPLIT), 256>>>();
    attn_out_kernel<<<dim3(Bc*Hh, Nn/TOK), 256>>>();

    gemm_mma<1><<<dim3(M_ROWS/128, Cc/192), 256, SMEM_TOTAL>>>(
        athi, atlo, wp, bproj, out);
}

// round 6
// speedup vs baseline: 5.4053x; 1.6631x over previous
#include <cuda_runtime.h>
#include <cuda_fp16.h>
#include <cstdint>

// ---------------------------------------------------------------------------
// Problem constants
// ---------------------------------------------------------------------------
#define Bc   8
#define Nn   4096
#define Cc   384
#define Hh   8
#define HD   48
#define KDIM 384
#define M_ROWS (Bc*Nn)    // 32768
#define QKV_COLS (3*Cc)   // 1152
#define NBH  (Bc*Hh)      // 64
#define DN 0.3799178428257963f   // 48^-0.25
#define KEPS 1e-3f
#define EPS  1e-8f

// ---------------------------------------------------------------------------
// Scratch (device globals; allocation APIs are forbidden)
// ---------------------------------------------------------------------------
__device__ float g_kptv32[NBH*HD*HD];          // [bh][d][m]
__device__ float g_ks32  [NBH*HD];

__device__ __align__(128) __half g_xh  [M_ROWS*KDIM];       // x fp16
__device__ __align__(128) __half g_wq  [QKV_COLS*KDIM];
__device__ __align__(128) __half g_wp  [Cc*KDIM];
__device__ __align__(128) __half g_qph [NBH*Nn*HD];         // [bh][n][48]
__device__ __align__(128) __half g_qpl [NBH*Nn*HD];
__device__ __align__(128) __half g_kpTh[NBH*HD*Nn];         // [bh][m][n]
__device__ __align__(128) __half g_kpTl[NBH*HD*Nn];
__device__ __align__(128) __half g_vTh [NBH*HD*Nn];         // [bh][d][n]
__device__ __align__(128) __half g_vTl [NBH*HD*Nn];
__device__ __align__(128) __half g_athi[M_ROWS*KDIM];       // attention out fp16
__device__ __align__(128) __half g_kvbh[NBH*64*HD];         // [bh][64][48] B for attn_out
__device__ __align__(128) __half g_kvbl[NBH*64*HD];

// ---------------------------------------------------------------------------
// PTX helpers
// ---------------------------------------------------------------------------
__device__ __forceinline__ uint32_t smem_u32(const void* p) {
    uint32_t a;
    asm("{ .reg .u64 t; cvta.to.shared.u64 t, %1; cvt.u32.u64 %0, t; }" : "=r"(a) : "l"(p));
    return a;
}
__device__ __forceinline__ void cp16(uint32_t s, const void* g) {
    asm volatile("cp.async.cg.shared.global [%0], [%1], 16;" :: "r"(s), "l"(g) : "memory");
}
__device__ __forceinline__ void cp_commit() { asm volatile("cp.async.commit_group;" ::: "memory"); }
template <int N> __device__ __forceinline__ void cp_wait() {
    asm volatile("cp.async.wait_group %0;" :: "n"(N) : "memory");
}
#define LDSM4(r, a) \
    asm volatile("ldmatrix.sync.aligned.m8n8.x4.shared.b16 {%0,%1,%2,%3}, [%4];" \
        : "=r"((r)[0]), "=r"((r)[1]), "=r"((r)[2]), "=r"((r)[3]) : "r"(a))
#define LDSM2(r, a) \
    asm volatile("ldmatrix.sync.aligned.m8n8.x2.shared.b16 {%0,%1}, [%2];" \
        : "=r"((r)[0]), "=r"((r)[1]) : "r"(a))

__device__ __forceinline__ void mma16816(float* c, const uint32_t* a, const uint32_t* b) {
    asm volatile(
        "mma.sync.aligned.m16n8k16.row.col.f32.f16.f16.f32 "
        "{%0,%1,%2,%3}, {%4,%5,%6,%7}, {%8,%9}, {%0,%1,%2,%3};"
        : "+f"(c[0]), "+f"(c[1]), "+f"(c[2]), "+f"(c[3])
        : "r"(a[0]), "r"(a[1]), "r"(a[2]), "r"(a[3]), "r"(b[0]), "r"(b[1]));
}

// ---------------------------------------------------------------------------
// prep kernels
// ---------------------------------------------------------------------------
__global__ void convert_x_kernel(const float* __restrict__ src, int n4) {
    int i = blockIdx.x * 256 + threadIdx.x;
    if (i >= n4) return;
    float4 v = ((const float4*)src)[i];
    ((__half2*)g_xh)[i*2]   = __half2(__float2half(v.x), __float2half(v.y));
    ((__half2*)g_xh)[i*2+1] = __half2(__float2half(v.z), __float2half(v.w));
}

__global__ void prep_w_kernel(const float* __restrict__ Wqkv,
                              const float* __restrict__ Wproj) {
    int i = blockIdx.x * 256 + threadIdx.x;
    if (i < QKV_COLS*KDIM) g_wq[i] = __float2half(Wqkv[i]);
    if (i < Cc*KDIM)       g_wp[i] = __float2half(Wproj[i]);
    if (i < NBH*HD*HD)     g_kptv32[i] = 0.f;
    if (i < NBH*HD)        g_ks32[i]   = 0.f;
}

// ---------------------------------------------------------------------------
// Single-fp16 tensor-core GEMM via mma.sync.
// C = A(M_ROWS x 384) @ W(cols x 384)^T
// CTA tile 128(M) x 192(N); 8 warps, warp tile 64x48. K chunks of 32, 3 stages.
// MODE 0: QKV feature-map epilogue (qp [n][48] hi/lo; kpT/vT [feat][n] hi/lo)
// MODE 1: out = acc + bias (fp32)
// ---------------------------------------------------------------------------
#define KC 32
#define A_ROW_B 80            // 40 halfs
#define OFF_W   10240         // 128*80
#define STG     25600         // 10240 + 192*80
#define NCH     (KDIM/KC)     // 12
#define SMEM_TOTAL 102912     // epilogue: 128*201*4

template <int MODE>
__global__ __launch_bounds__(256) void gemm_mma(
    const __half* __restrict__ A, const __half* __restrict__ W,
    const float* __restrict__ bias, float* __restrict__ out)
{
    extern __shared__ char smem[];
    const uint32_t sb = smem_u32(smem);
    const int tid = threadIdx.x;
    const int wid = tid >> 5;
    const int l   = tid & 31;
    const int wm  = wid & 1;
    const int wn  = wid >> 1;
    const int row0 = blockIdx.x * 128;
    const int col0 = blockIdx.y * 192;

    auto load_chunk = [&](int L, int s) {
        const uint32_t st = sb + s * STG;
        const int kof = L * KC;
        #pragma unroll
        for (int i = 0; i < 2; i++) {            // A: 128 rows x 4 segs
            int idx = tid + i * 256;
            int row = idx >> 2, seg = idx & 3;
            cp16(st + (uint32_t)(row * A_ROW_B + seg * 16),
                 A + (size_t)(row0 + row) * KDIM + kof + seg * 8);
        }
        #pragma unroll
        for (int i = 0; i < 3; i++) {            // W: 192 rows x 4 segs
            int idx = tid + i * 256;
            int row = idx >> 2, seg = idx & 3;
            cp16(st + OFF_W + (uint32_t)(row * A_ROW_B + seg * 16),
                 W + (size_t)(col0 + row) * KDIM + kof + seg * 8);
        }
        cp_commit();
    };

    const uint32_t a_base = (uint32_t)(((wm*64 + (l & 15)) * 40 + (l >> 4) * 8) * 2);
    const uint32_t b_base = (uint32_t)(((wn*48 + ((l >> 4) & 1) * 8 + (l & 7)) * 40
                                        + ((l >> 3) & 1) * 8) * 2);

    float acc[4][6][4];
    #pragma unroll
    for (int mt = 0; mt < 4; mt++)
        #pragma unroll
        for (int nt = 0; nt < 6; nt++)
            #pragma unroll
            for (int r = 0; r < 4; r++) acc[mt][nt][r] = 0.f;

    load_chunk(0, 0);
    load_chunk(1, 1);
    load_chunk(2, 2);

    #pragma unroll 1
    for (int c = 0; c < NCH; c++) {
        if (c < NCH - 2)      cp_wait<2>();
        else if (c == NCH-2)  cp_wait<1>();
        else                  cp_wait<0>();
        __syncthreads();
        const uint32_t st = sb + (c % 3) * STG;

        #pragma unroll
        for (int ks = 0; ks < 2; ks++) {
            const uint32_t ko = ks * 32;
            uint32_t ah[4][4], bh[3][4];
            #pragma unroll
            for (int np = 0; np < 3; np++)
                LDSM4(bh[np], st + OFF_W + b_base + np*1280 + ko);
            #pragma unroll
            for (int mt = 0; mt < 4; mt++)
                LDSM4(ah[mt], st + a_base + mt*1280 + ko);
            #pragma unroll
            for (int mt = 0; mt < 4; mt++)
                #pragma unroll
                for (int np = 0; np < 3; np++)
                    #pragma unroll
                    for (int hf = 0; hf < 2; hf++)
                        mma16816(acc[mt][np*2 + hf], ah[mt], &bh[np][hf*2]);
        }
        __syncthreads();
        if (c + 3 < NCH) load_chunk(c + 3, c % 3);
    }

    // ---- epilogue via smem [128][201] fp32 (odd pad: conflict-free both axes;
    //      scalar stores only — odd pad breaks float2 alignment) ----
    float* epi = (float*)smem;
    const int g   = l >> 2;
    const int tig = l & 3;
    #pragma unroll
    for (int mt = 0; mt < 4; mt++)
        #pragma unroll
        for (int nt = 0; nt < 6; nt++) {
            int row = wm*64 + mt*16 + g;
            int col = wn*48 + nt*8 + 2*tig;
            epi[row * 201 + col]           = acc[mt][nt][0];
            epi[row * 201 + col + 1]       = acc[mt][nt][1];
            epi[(row + 8) * 201 + col]     = acc[mt][nt][2];
            epi[(row + 8) * 201 + col + 1] = acc[mt][nt][3];
        }
    __syncthreads();

    if (MODE == 0) {
        const int b  = row0 >> 12;
        const int n0 = row0 & (Nn - 1);
        #pragma unroll
        for (int g4 = 0; g4 < 4; g4++) {
            const int gg = blockIdx.y * 4 + g4;
            const int sI = gg >> 3;        // 0=q,1=k,2=v
            const int h  = gg & 7;
            const int bh = b * Hh + h;
            if (sI == 0) {
                // qp: [bh][n][48] hi/lo with feature map
                const size_t base = ((size_t)bh * Nn + n0) * HD;
                #pragma unroll 4
                for (int it = 0; it < 24; it++) {
                    int idx = tid + it * 256;
                    int m = idx / 48, e = idx - m * 48;
                    float v = epi[m * 201 + g4 * 48 + e];
                    v = fmaxf(v * DN, 0.f) + KEPS;
                    __half hi = __float2half(v);
                    g_qph[base + idx] = hi;
                    g_qpl[base + idx] = __float2half(v - __half2float(hi));
                }
            } else {
                // kpT / vT: [bh][feat][n] hi/lo (transposed store)
                __half* Ph = (sI == 1) ? g_kpTh : g_vTh;
                __half* Pl = (sI == 1) ? g_kpTl : g_vTl;
                const size_t base = (size_t)bh * HD * Nn;
                #pragma unroll 4
                for (int it = 0; it < 24; it++) {
                    int idx = tid + it * 256;
                    int e = idx >> 7, m = idx & 127;
                    float v = epi[m * 201 + g4 * 48 + e];
                    if (sI == 1) v = fmaxf(v * DN, 0.f) + KEPS;
                    __half hi = __float2half(v);
                    size_t off = base + (size_t)e * Nn + n0 + m;
                    Ph[off] = hi;
                    Pl[off] = __float2half(v - __half2float(hi));
                }
            }
        }
    } else {
        #pragma unroll 8
        for (int it = 0; it < 96; it++) {
            int idx = tid + it * 256;
            int m = idx / 192, j = idx - m * 192;
            out[(size_t)(row0 + m) * Cc + col0 + j] = epi[m * 201 + j] + bias[col0 + j];
        }
    }
}

// ---------------------------------------------------------------------------
// kv_agg on tensor cores: per (bh, split): C[64 x 48] += Arows @ kpT^T over n,
// A rows 0-47 = vT (d), row 48 = ones (-> ks), rows 49-63 = 0.
// 3-term hi/lo split (exact to ~2^-22). K chunks of 64 n, 3-stage cp.async.
// ---------------------------------------------------------------------------
#define KC2 64
#define SPLITK 4
#define NCH2 ((Nn/SPLITK)/KC2)   // 16
#define AROWB2 144               // 72 halfs
#define OFF2_AL 9216             // 64*144
#define OFF2_BH 18432
#define OFF2_BL 25344            // +48*144
#define STG2   32256
#define SMEM2  (3*STG2)          // 96768

__global__ __launch_bounds__(256) void kv_agg_mma()
{
    extern __shared__ char smem[];
    const uint32_t sb = smem_u32(smem);
    const int tid = threadIdx.x;
    const int wid = tid >> 5;
    const int l   = tid & 31;
    const int bh  = blockIdx.x;
    const int n_base = blockIdx.y * (Nn / SPLITK);

    // preset constant A rows 48-63 in all 3 stages (row 48 hi = 1, rest 0)
    for (int i = tid; i < 3 * 16 * 64; i += 256) {
        int s = i / 1024, rr = (i >> 6) & 15, cc = i & 63;
        __half vh = (rr == 0) ? __float2half(1.f) : __float2half(0.f);
        *(__half*)(smem + s*STG2 + (48 + rr)*AROWB2 + cc*2) = vh;
        *(__half*)(smem + s*STG2 + OFF2_AL + (48 + rr)*AROWB2 + cc*2) = __float2half(0.f);
    }
    __syncthreads();

    const __half* srcs[4] = { g_vTh  + (size_t)bh*HD*Nn, g_vTl  + (size_t)bh*HD*Nn,
                              g_kpTh + (size_t)bh*HD*Nn, g_kpTl + (size_t)bh*HD*Nn };
    const uint32_t offs[4] = { 0, OFF2_AL, OFF2_BH, OFF2_BL };

    auto load_chunk = [&](int ch, int s) {
        const uint32_t st = sb + s * STG2;
        const int n0 = n_base + ch * KC2;
        #pragma unroll
        for (int i = 0; i < 6; i++) {
            int idx = tid + i * 256;          // 0..1535
            int arr = idx / 384;
            int rem = idx - arr * 384;
            int row = rem >> 3, seg = rem & 7;
            cp16(st + offs[arr] + (uint32_t)(row * AROWB2 + seg * 16),
                 srcs[arr] + (size_t)row * Nn + n0 + seg * 8);
        }
        cp_commit();
    };

    const int wm = wid & 3;       // 4 M-tiles of 16
    const int wn = wid >> 2;      // 2 N-halves of 24
    const uint32_t a_base  = (uint32_t)((wm*16 + (l & 15)) * AROWB2 + (l >> 4) * 16);
    const uint32_t b16     = (uint32_t)((wn*24 + ((l >> 4) & 1)*8 + (l & 7)) * AROWB2
                                        + ((l >> 3) & 1) * 16);
    const uint32_t b8      = (uint32_t)((wn*24 + 16 + (l & 7)) * AROWB2
                                        + ((l >> 3) & 1) * 16);

    float acc[3][4];
    #pragma unroll
    for (int nt = 0; nt < 3; nt++)
        #pragma unroll
        for (int r = 0; r < 4; r++) acc[nt][r] = 0.f;

    load_chunk(0, 0);
    load_chunk(1, 1);
    load_chunk(2, 2);

    #pragma unroll 1
    for (int c = 0; c < NCH2; c++) {
        if (c < NCH2 - 2)      cp_wait<2>();
        else if (c == NCH2-2)  cp_wait<1>();
        else                   cp_wait<0>();
        __syncthreads();
        const uint32_t st = sb + (c % 3) * STG2;

        #pragma unroll
        for (int ks = 0; ks < 4; ks++) {
            const uint32_t ko = ks * 32;
            uint32_t ah[4], al[4], bh01[4], bl01[4], bh2[2], bl2[2];
            LDSM4(ah,   st + a_base + ko);
            LDSM4(al,   st + OFF2_AL + a_base + ko);
            LDSM4(bh01, st + OFF2_BH + b16 + ko);
            LDSM4(bl01, st + OFF2_BL + b16 + ko);
            LDSM2(bh2,  st + OFF2_BH + b8 + ko);
            LDSM2(bl2,  st + OFF2_BL + b8 + ko);
            mma16816(acc[0], ah, &bh01[0]); mma16816(acc[0], ah, &bl01[0]); mma16816(acc[0], al, &bh01[0]);
            mma16816(acc[1], ah, &bh01[2]); mma16816(acc[1], ah, &bl01[2]); mma16816(acc[1], al, &bh01[2]);
            mma16816(acc[2], ah, bh2);      mma16816(acc[2], ah, bl2);      mma16816(acc[2], al, bh2);
        }
        __syncthreads();
        if (c + 3 < NCH2) load_chunk(c + 3, c % 3);
    }

    // epilogue: atomic reduce. C row = d (or 48 -> ks), col = m.
    const int rowg = wm*16 + (l >> 2);
    #pragma unroll
    for (int nt = 0; nt < 3; nt++) {
        int col = wn*24 + nt*8 + (l & 3)*2;
        #pragma unroll
        for (int rr = 0; rr < 2; rr++) {
            int d = rowg + rr*8;
            if (d < HD) {
                atomicAdd(&g_kptv32[((size_t)bh*HD + d)*HD + col],     acc[nt][rr*2]);
                atomicAdd(&g_kptv32[((size_t)bh*HD + d)*HD + col + 1], acc[nt][rr*2+1]);
            } else if (d == HD) {
                atomicAdd(&g_ks32[bh*HD + col],     acc[nt][rr*2]);
                atomicAdd(&g_ks32[bh*HD + col + 1], acc[nt][rr*2+1]);
            }
        }
    }
}

// ---------------------------------------------------------------------------
// convert kptv/ks -> fp16 hi/lo B matrix [bh][64][48] (row 48 = ks, rest pad 0)
// ---------------------------------------------------------------------------
__global__ void kvb_conv_kernel()
{
    const int bh = blockIdx.x;
    for (int i = threadIdx.x; i < 64*HD; i += 256) {
        int d = i / HD, m = i - d*HD;
        float v = (d < HD) ? g_kptv32[((size_t)bh*HD + d)*HD + m]
                 : (d == HD) ? g_ks32[bh*HD + m] : 0.f;
        __half hi = __float2half(v);
        g_kvbh[bh*64*HD + i] = hi;
        g_kvbl[bh*64*HD + i] = __float2half(v - __half2float(hi));
    }
}

// ---------------------------------------------------------------------------
// attn_out on tensor cores: per (bh, 256-token block):
// C[256 x 64] = qp(256x48) @ Bt(64x48)^T ; col 48 = D; att = C[:, :48]/(D+eps)
// 3-term hi/lo. Single-shot smem load (no pipeline; 1024 CTAs hide latency).
// ---------------------------------------------------------------------------
#define AO_ROWB 112          // 56 halfs
#define AO_AL 28672          // 256*112
#define AO_BH 57344
#define AO_BL 64512          // +64*112
#define AO_SMEM 71680

__global__ __launch_bounds__(256) void attn_out_mma()
{
    extern __shared__ char smem[];
    const uint32_t sb = smem_u32(smem);
    const int tid = threadIdx.x;
    const int wid = tid >> 5;
    const int l   = tid & 31;
    const int bh  = blockIdx.x;
    const int n0  = blockIdx.y * 256;

    // load A (qp hi/lo): 256 rows x 6 segs x 2
    #pragma unroll
    for (int i = 0; i < 12; i++) {
        int idx = tid + i * 256;
        int arr = idx / 1536;
        int rem = idx - arr * 1536;
        int row = rem / 6, seg = rem - row * 6;
        const __half* src = arr ? g_qpl : g_qph;
        cp16(sb + (arr ? AO_AL : 0) + (uint32_t)(row * AO_ROWB + seg * 16),
             src + ((size_t)bh * Nn + n0 + row) * HD + seg * 8);
    }
    // load B (kvb hi/lo): 64 rows x 6 segs x 2
    #pragma unroll
    for (int i = 0; i < 3; i++) {
        int idx = tid + i * 256;
        int arr = idx / 384;
        int rem = idx - arr * 384;
        int row = rem / 6, seg = rem - row * 6;
        const __half* src = arr ? g_kvbl : g_kvbh;
        cp16(sb + (arr ? AO_BL : AO_BH) + (uint32_t)(row * AO_ROWB + seg * 16),
             src + bh*64*HD + row * HD + seg * 8);
    }
    cp_commit();
    cp_wait<0>();
    __syncthreads();

    float acc[2][7][4];
    #pragma unroll
    for (int mt = 0; mt < 2; mt++)
        #pragma unroll
        for (int nt = 0; nt < 7; nt++)
            #pragma unroll
            for (int r = 0; r < 4; r++) acc[mt][nt][r] = 0.f;

    const uint32_t a_base = (uint32_t)((wid*32 + (l & 15)) * AO_ROWB + (l >> 4) * 16);
    const uint32_t b_base = (uint32_t)((((l >> 4) & 1)*8 + (l & 7)) * AO_ROWB
                                       + ((l >> 3) & 1) * 16);

    #pragma unroll
    for (int k = 0; k < 3; k++) {
        const uint32_t ko = k * 32;
        uint32_t bhf[4][4], blf[4][4];
        #pragma unroll
        for (int bt = 0; bt < 4; bt++) {
            LDSM4(bhf[bt], sb + AO_BH + b_base + bt*16*AO_ROWB + ko);
            LDSM4(blf[bt], sb + AO_BL + b_base + bt*16*AO_ROWB + ko);
        }
        #pragma unroll
        for (int mt = 0; mt < 2; mt++) {
            uint32_t ah[4], al[4];
            LDSM4(ah, sb + a_base + mt*16*AO_ROWB + ko);
            LDSM4(al, sb + AO_AL + a_base + mt*16*AO_ROWB + ko);
            #pragma unroll
            for (int nt = 0; nt < 7; nt++) {   // nt 6 = D column (48..55)
                const uint32_t* bsh = &bhf[nt >> 1][(nt & 1)*2];
                const uint32_t* bsl = &blf[nt >> 1][(nt & 1)*2];
                mma16816(acc[mt][nt], ah, bsh);
                mma16816(acc[mt][nt], ah, bsl);
                mma16816(acc[mt][nt], al, bsh);
            }
        }
    }

    // epilogue: D = col 48 (tile 6 col 0, lanes l&3==0); divide, store fp16
    #pragma unroll
    for (int mt = 0; mt < 2; mt++) {
        float D0 = __shfl_sync(0xFFFFFFFFu, acc[mt][6][0], l & 0x1C);
        float D1 = __shfl_sync(0xFFFFFFFFu, acc[mt][6][2], l & 0x1C);
        float inv0 = 1.f / (D0 + EPS);
        float inv1 = 1.f / (D1 + EPS);
        int r0 = wid*32 + mt*16 + (l >> 2);
        size_t rowbase0 = ((size_t)bh * Nn + n0 + r0) * HD;
        size_t rowbase1 = ((size_t)bh * Nn + n0 + r0 + 8) * HD;
        #pragma unroll
        for (int nt = 0; nt < 6; nt++) {
            int col = nt*8 + (l & 3)*2;
            __half2 h0 = __half2(__float2half(acc[mt][nt][0]*inv0),
                                 __float2half(acc[mt][nt][1]*inv0));
            __half2 h1 = __half2(__float2half(acc[mt][nt][2]*inv1),
                                 __float2half(acc[mt][nt][3]*inv1));
            *(__half2*)&g_athi[rowbase0 + col] = h0;
            *(__half2*)&g_athi[rowbase1 + col] = h1;
        }
    }
}

// ---------------------------------------------------------------------------
extern "C" void kernel_launch(void* const* d_in, const int* in_sizes, int n_in,
                              void* d_out, int out_size)
{
    (void)in_sizes; (void)n_in; (void)out_size;
    const float* x     = (const float*)d_in[0];
    const float* Wqkv  = (const float*)d_in[1];
    const float* Wproj = (const float*)d_in[2];
    const float* bproj = (const float*)d_in[3];
    float* out = (float*)d_out;

    cudaFuncSetAttribute(gemm_mma<0>, cudaFuncAttributeMaxDynamicSharedMemorySize, SMEM_TOTAL);
    cudaFuncSetAttribute(gemm_mma<1>, cudaFuncAttributeMaxDynamicSharedMemorySize, SMEM_TOTAL);
    cudaFuncSetAttribute(kv_agg_mma,  cudaFuncAttributeMaxDynamicSharedMemorySize, SMEM2);
    cudaFuncSetAttribute(attn_out_mma, cudaFuncAttributeMaxDynamicSharedMemorySize, AO_SMEM);

    __half *xh, *wq, *wp, *athi;
    cudaGetSymbolAddress((void**)&xh,   g_xh);
    cudaGetSymbolAddress((void**)&wq,   g_wq);
    cudaGetSymbolAddress((void**)&wp,   g_wp);
    cudaGetSymbolAddress((void**)&athi, g_athi);

    convert_x_kernel<<<(M_ROWS*KDIM/4 + 255)/256, 256>>>(x, M_ROWS*KDIM/4);
    prep_w_kernel<<<(QKV_COLS*KDIM + 255)/256, 256>>>(Wqkv, Wproj);

    gemm_mma<0><<<dim3(M_ROWS/128, QKV_COLS/192), 256, SMEM_TOTAL>>>(
        xh, wq, nullptr, nullptr);

    kv_agg_mma<<<dim3(NBH, SPLITK), 256, SMEM2>>>();
    kvb_conv_kernel<<<NBH, 256>>>();
    attn_out_mma<<<dim3(NBH, Nn/256), 256, AO_SMEM>>>();

    gemm_mma<1><<<dim3(M_ROWS/128, Cc/192), 256, SMEM_TOTAL>>>(
        athi, wp, bproj, out);
}

// round 7
// speedup vs baseline: 6.0257x; 1.1148x over previous
#include <cuda_runtime.h>
#include <cuda_fp16.h>
#include <cstdint>

// ---------------------------------------------------------------------------
// Problem constants
// ---------------------------------------------------------------------------
#define Bc   8
#define Nn   4096
#define Cc   384
#define Hh   8
#define HD   48
#define KDIM 384
#define M_ROWS (Bc*Nn)    // 32768
#define QKV_COLS (3*Cc)   // 1152
#define NBH  (Bc*Hh)      // 64
#define DN 0.3799178428257963f   // 48^-0.25
#define KEPS 1e-3f
#define EPS  1e-8f

// ---------------------------------------------------------------------------
// Scratch (device globals; allocation APIs are forbidden)
// ---------------------------------------------------------------------------
__device__ float g_kptv32[NBH*HD*HD];          // [bh][d][m]
__device__ float g_ks32  [NBH*HD];

__device__ __align__(128) __half g_xh  [M_ROWS*KDIM];       // x fp16
__device__ __align__(128) __half g_wq  [QKV_COLS*KDIM];
__device__ __align__(128) __half g_wp  [Cc*KDIM];
__device__ __align__(128) __half g_qph [NBH*Nn*HD];         // [bh][n][48]
__device__ __align__(128) __half g_kpTh[NBH*HD*Nn];         // [bh][m][n]
__device__ __align__(128) __half g_vTh [NBH*HD*Nn];         // [bh][d][n]
__device__ __align__(128) __half g_athi[M_ROWS*KDIM];       // attention out fp16
__device__ __align__(128) __half g_kvbh[NBH*64*HD];         // [bh][64][48] B for attn_out

// ---------------------------------------------------------------------------
// PTX helpers
// ---------------------------------------------------------------------------
__device__ __forceinline__ uint32_t smem_u32(const void* p) {
    uint32_t a;
    asm("{ .reg .u64 t; cvta.to.shared.u64 t, %1; cvt.u32.u64 %0, t; }" : "=r"(a) : "l"(p));
    return a;
}
__device__ __forceinline__ void cp16(uint32_t s, const void* g) {
    asm volatile("cp.async.cg.shared.global [%0], [%1], 16;" :: "r"(s), "l"(g) : "memory");
}
__device__ __forceinline__ void cp_commit() { asm volatile("cp.async.commit_group;" ::: "memory"); }
template <int N> __device__ __forceinline__ void cp_wait() {
    asm volatile("cp.async.wait_group %0;" :: "n"(N) : "memory");
}
#define LDSM4(r, a) \
    asm volatile("ldmatrix.sync.aligned.m8n8.x4.shared.b16 {%0,%1,%2,%3}, [%4];" \
        : "=r"((r)[0]), "=r"((r)[1]), "=r"((r)[2]), "=r"((r)[3]) : "r"(a))
#define LDSM2(r, a) \
    asm volatile("ldmatrix.sync.aligned.m8n8.x2.shared.b16 {%0,%1}, [%2];" \
        : "=r"((r)[0]), "=r"((r)[1]) : "r"(a))

__device__ __forceinline__ void mma16816(float* c, const uint32_t* a, const uint32_t* b) {
    asm volatile(
        "mma.sync.aligned.m16n8k16.row.col.f32.f16.f16.f32 "
        "{%0,%1,%2,%3}, {%4,%5,%6,%7}, {%8,%9}, {%0,%1,%2,%3};"
        : "+f"(c[0]), "+f"(c[1]), "+f"(c[2]), "+f"(c[3])
        : "r"(a[0]), "r"(a[1]), "r"(a[2]), "r"(a[3]), "r"(b[0]), "r"(b[1]));
}

// ---------------------------------------------------------------------------
// prep kernels
// ---------------------------------------------------------------------------
__global__ void convert_x_kernel(const float* __restrict__ src, int n4) {
    int i = blockIdx.x * 256 + threadIdx.x;
    if (i >= n4) return;
    float4 v = ((const float4*)src)[i];
    ((__half2*)g_xh)[i*2]   = __half2(__float2half(v.x), __float2half(v.y));
    ((__half2*)g_xh)[i*2+1] = __half2(__float2half(v.z), __float2half(v.w));
}

__global__ void prep_w_kernel(const float* __restrict__ Wqkv,
                              const float* __restrict__ Wproj) {
    int i = blockIdx.x * 256 + threadIdx.x;
    if (i < QKV_COLS*KDIM) g_wq[i] = __float2half(Wqkv[i]);
    if (i < Cc*KDIM)       g_wp[i] = __float2half(Wproj[i]);
    if (i < NBH*HD*HD)     g_kptv32[i] = 0.f;
    if (i < NBH*HD)        g_ks32[i]   = 0.f;
}

// ---------------------------------------------------------------------------
// Single-fp16 tensor-core GEMM via mma.sync.
// C = A(M_ROWS x 384) @ W(cols x 384)^T
// CTA tile 128(M) x 192(N); 8 warps, warp tile 64x48. K chunks of 32, 3 stages.
// MODE 0: QKV feature-map epilogue (qp [n][48]; kpT/vT [feat][n])
// MODE 1: out = acc + bias (fp32)
// ---------------------------------------------------------------------------
#define KC 32
#define A_ROW_B 80            // 40 halfs
#define OFF_W   10240         // 128*80
#define STG     25600         // 10240 + 192*80
#define NCH     (KDIM/KC)     // 12
#define SMEM_TOTAL 102912     // epilogue: 128*201*4

template <int MODE>
__global__ __launch_bounds__(256) void gemm_mma(
    const __half* __restrict__ A, const __half* __restrict__ W,
    const float* __restrict__ bias, float* __restrict__ out)
{
    extern __shared__ char smem[];
    const uint32_t sb = smem_u32(smem);
    const int tid = threadIdx.x;
    const int wid = tid >> 5;
    const int l   = tid & 31;
    const int wm  = wid & 1;
    const int wn  = wid >> 1;
    const int row0 = blockIdx.x * 128;
    const int col0 = blockIdx.y * 192;

    auto load_chunk = [&](int L, int s) {
        const uint32_t st = sb + s * STG;
        const int kof = L * KC;
        #pragma unroll
        for (int i = 0; i < 2; i++) {            // A: 128 rows x 4 segs
            int idx = tid + i * 256;
            int row = idx >> 2, seg = idx & 3;
            cp16(st + (uint32_t)(row * A_ROW_B + seg * 16),
                 A + (size_t)(row0 + row) * KDIM + kof + seg * 8);
        }
        #pragma unroll
        for (int i = 0; i < 3; i++) {            // W: 192 rows x 4 segs
            int idx = tid + i * 256;
            int row = idx >> 2, seg = idx & 3;
            cp16(st + OFF_W + (uint32_t)(row * A_ROW_B + seg * 16),
                 W + (size_t)(col0 + row) * KDIM + kof + seg * 8);
        }
        cp_commit();
    };

    const uint32_t a_base = (uint32_t)(((wm*64 + (l & 15)) * 40 + (l >> 4) * 8) * 2);
    const uint32_t b_base = (uint32_t)(((wn*48 + ((l >> 4) & 1) * 8 + (l & 7)) * 40
                                        + ((l >> 3) & 1) * 8) * 2);

    float acc[4][6][4];
    #pragma unroll
    for (int mt = 0; mt < 4; mt++)
        #pragma unroll
        for (int nt = 0; nt < 6; nt++)
            #pragma unroll
            for (int r = 0; r < 4; r++) acc[mt][nt][r] = 0.f;

    load_chunk(0, 0);
    load_chunk(1, 1);
    load_chunk(2, 2);

    #pragma unroll 1
    for (int c = 0; c < NCH; c++) {
        if (c < NCH - 2)      cp_wait<2>();
        else if (c == NCH-2)  cp_wait<1>();
        else                  cp_wait<0>();
        __syncthreads();
        const uint32_t st = sb + (c % 3) * STG;

        #pragma unroll
        for (int ks = 0; ks < 2; ks++) {
            const uint32_t ko = ks * 32;
            uint32_t ah[4][4], bh[3][4];
            #pragma unroll
            for (int np = 0; np < 3; np++)
                LDSM4(bh[np], st + OFF_W + b_base + np*1280 + ko);
            #pragma unroll
            for (int mt = 0; mt < 4; mt++)
                LDSM4(ah[mt], st + a_base + mt*1280 + ko);
            #pragma unroll
            for (int mt = 0; mt < 4; mt++)
                #pragma unroll
                for (int np = 0; np < 3; np++)
                    #pragma unroll
                    for (int hf = 0; hf < 2; hf++)
                        mma16816(acc[mt][np*2 + hf], ah[mt], &bh[np][hf*2]);
        }
        __syncthreads();
        if (c + 3 < NCH) load_chunk(c + 3, c % 3);
    }

    // ---- epilogue via smem [128][201] fp32 (odd pad: conflict-free both axes;
    //      scalar stores only — odd pad breaks float2 alignment) ----
    float* epi = (float*)smem;
    const int g   = l >> 2;
    const int tig = l & 3;
    #pragma unroll
    for (int mt = 0; mt < 4; mt++)
        #pragma unroll
        for (int nt = 0; nt < 6; nt++) {
            int row = wm*64 + mt*16 + g;
            int col = wn*48 + nt*8 + 2*tig;
            epi[row * 201 + col]           = acc[mt][nt][0];
            epi[row * 201 + col + 1]       = acc[mt][nt][1];
            epi[(row + 8) * 201 + col]     = acc[mt][nt][2];
            epi[(row + 8) * 201 + col + 1] = acc[mt][nt][3];
        }
    __syncthreads();

    if (MODE == 0) {
        const int b  = row0 >> 12;
        const int n0 = row0 & (Nn - 1);
        #pragma unroll
        for (int g4 = 0; g4 < 4; g4++) {
            const int gg = blockIdx.y * 4 + g4;
            const int sI = gg >> 3;        // 0=q,1=k,2=v
            const int h  = gg & 7;
            const int bh = b * Hh + h;
            if (sI == 0) {
                // qp: [bh][n][48] with feature map
                const size_t base = ((size_t)bh * Nn + n0) * HD;
                #pragma unroll 4
                for (int it = 0; it < 24; it++) {
                    int idx = tid + it * 256;
                    int m = idx / 48, e = idx - m * 48;
                    float v = epi[m * 201 + g4 * 48 + e];
                    v = fmaxf(v * DN, 0.f) + KEPS;
                    g_qph[base + idx] = __float2half(v);
                }
            } else {
                // kpT / vT: [bh][feat][n] (transposed store)
                __half* Ph = (sI == 1) ? g_kpTh : g_vTh;
                const size_t base = (size_t)bh * HD * Nn;
                #pragma unroll 4
                for (int it = 0; it < 24; it++) {
                    int idx = tid + it * 256;
                    int e = idx >> 7, m = idx & 127;
                    float v = epi[m * 201 + g4 * 48 + e];
                    if (sI == 1) v = fmaxf(v * DN, 0.f) + KEPS;
                    Ph[base + (size_t)e * Nn + n0 + m] = __float2half(v);
                }
            }
        }
    } else {
        #pragma unroll 8
        for (int it = 0; it < 96; it++) {
            int idx = tid + it * 256;
            int m = idx / 192, j = idx - m * 192;
            out[(size_t)(row0 + m) * Cc + col0 + j] = epi[m * 201 + j] + bias[col0 + j];
        }
    }
}

// ---------------------------------------------------------------------------
// kv_agg on tensor cores (single fp16): per (bh, split):
// C[64 x 48] += Arows @ kpT^T over n; A rows 0-47 = vT, row 48 = ones (-> ks).
// K chunks of 64 n, 3-stage cp.async, split-K 8.
// ---------------------------------------------------------------------------
#define KC2 64
#define SPLITK 8
#define NCH2 ((Nn/SPLITK)/KC2)   // 8
#define AROWB2 144               // 72 halfs
#define OFF2_B 9216              // 64*144
#define STG2   16128             // 9216 + 48*144
#define SMEM2  (3*STG2)          // 48384

__global__ __launch_bounds__(256) void kv_agg_mma()
{
    extern __shared__ char smem[];
    const uint32_t sb = smem_u32(smem);
    const int tid = threadIdx.x;
    const int wid = tid >> 5;
    const int l   = tid & 31;
    const int bh  = blockIdx.x;
    const int n_base = blockIdx.y * (Nn / SPLITK);

    // preset constant A rows 48-63 in all 3 stages (row 48 = 1, rest 0)
    for (int i = tid; i < 3 * 16 * 64; i += 256) {
        int s = i / 1024, rr = (i >> 6) & 15, cc = i & 63;
        *(__half*)(smem + s*STG2 + (48 + rr)*AROWB2 + cc*2) =
            (rr == 0) ? __float2half(1.f) : __float2half(0.f);
    }
    __syncthreads();

    const __half* vT  = g_vTh  + (size_t)bh*HD*Nn;
    const __half* kpT = g_kpTh + (size_t)bh*HD*Nn;

    auto load_chunk = [&](int ch, int s) {
        const uint32_t st = sb + s * STG2;
        const int n0 = n_base + ch * KC2;
        #pragma unroll
        for (int i = 0; i < 3; i++) {
            int idx = tid + i * 256;          // 0..767
            int arr = idx / 384;              // 0 = vT, 1 = kpT
            int rem = idx - arr * 384;
            int row = rem >> 3, seg = rem & 7;
            cp16(st + (arr ? OFF2_B : 0) + (uint32_t)(row * AROWB2 + seg * 16),
                 (arr ? kpT : vT) + (size_t)row * Nn + n0 + seg * 8);
        }
        cp_commit();
    };

    const int wm = wid & 3;       // 4 M-tiles of 16
    const int wn = wid >> 2;      // 2 N-halves of 24
    const uint32_t a_base  = (uint32_t)((wm*16 + (l & 15)) * AROWB2 + (l >> 4) * 16);
    const uint32_t b16     = (uint32_t)((wn*24 + ((l >> 4) & 1)*8 + (l & 7)) * AROWB2
                                        + ((l >> 3) & 1) * 16);
    const uint32_t b8      = (uint32_t)((wn*24 + 16 + (l & 7)) * AROWB2
                                        + ((l >> 3) & 1) * 16);

    float acc[3][4];
    #pragma unroll
    for (int nt = 0; nt < 3; nt++)
        #pragma unroll
        for (int r = 0; r < 4; r++) acc[nt][r] = 0.f;

    load_chunk(0, 0);
    load_chunk(1, 1);
    load_chunk(2, 2);

    #pragma unroll 1
    for (int c = 0; c < NCH2; c++) {
        if (c < NCH2 - 2)      cp_wait<2>();
        else if (c == NCH2-2)  cp_wait<1>();
        else                   cp_wait<0>();
        __syncthreads();
        const uint32_t st = sb + (c % 3) * STG2;

        #pragma unroll
        for (int ks = 0; ks < 4; ks++) {
            const uint32_t ko = ks * 32;
            uint32_t ah[4], bh01[4], bh2[2];
            LDSM4(ah,   st + a_base + ko);
            LDSM4(bh01, st + OFF2_B + b16 + ko);
            LDSM2(bh2,  st + OFF2_B + b8 + ko);
            mma16816(acc[0], ah, &bh01[0]);
            mma16816(acc[1], ah, &bh01[2]);
            mma16816(acc[2], ah, bh2);
        }
        __syncthreads();
        if (c + 3 < NCH2) load_chunk(c + 3, c % 3);
    }

    // epilogue: atomic reduce. C row = d (or 48 -> ks), col = m.
    const int rowg = wm*16 + (l >> 2);
    #pragma unroll
    for (int nt = 0; nt < 3; nt++) {
        int col = wn*24 + nt*8 + (l & 3)*2;
        #pragma unroll
        for (int rr = 0; rr < 2; rr++) {
            int d = rowg + rr*8;
            if (d < HD) {
                atomicAdd(&g_kptv32[((size_t)bh*HD + d)*HD + col],     acc[nt][rr*2]);
                atomicAdd(&g_kptv32[((size_t)bh*HD + d)*HD + col + 1], acc[nt][rr*2+1]);
            } else if (d == HD) {
                atomicAdd(&g_ks32[bh*HD + col],     acc[nt][rr*2]);
                atomicAdd(&g_ks32[bh*HD + col + 1], acc[nt][rr*2+1]);
            }
        }
    }
}

// ---------------------------------------------------------------------------
// convert kptv/ks -> fp16 B matrix [bh][64][48] (row 48 = ks, rest pad 0)
// ---------------------------------------------------------------------------
__global__ void kvb_conv_kernel()
{
    const int bh = blockIdx.x;
    for (int i = threadIdx.x; i < 64*HD; i += 256) {
        int d = i / HD, m = i - d*HD;
        float v = (d < HD) ? g_kptv32[((size_t)bh*HD + d)*HD + m]
                 : (d == HD) ? g_ks32[bh*HD + m] : 0.f;
        g_kvbh[bh*64*HD + i] = __float2half(v);
    }
}

// ---------------------------------------------------------------------------
// attn_out on tensor cores (single fp16): per (bh, 256-token block):
// C[256 x 64] = qp(256x48) @ Bt(64x48)^T ; col 48 = D; att = C[:, :48]/(D+eps)
// ---------------------------------------------------------------------------
#define AO_ROWB 112          // 56 halfs
#define AO_B  28672          // 256*112
#define AO_SMEM 35840        // + 64*112

__global__ __launch_bounds__(256) void attn_out_mma()
{
    extern __shared__ char smem[];
    const uint32_t sb = smem_u32(smem);
    const int tid = threadIdx.x;
    const int wid = tid >> 5;
    const int l   = tid & 31;
    const int bh  = blockIdx.x;
    const int n0  = blockIdx.y * 256;

    // load A (qp): 256 rows x 6 segs
    #pragma unroll
    for (int i = 0; i < 6; i++) {
        int idx = tid + i * 256;
        int row = idx / 6, seg = idx - row * 6;
        cp16(sb + (uint32_t)(row * AO_ROWB + seg * 16),
             g_qph + ((size_t)bh * Nn + n0 + row) * HD + seg * 8);
    }
    // load B (kvb): 64 rows x 6 segs = 384
    #pragma unroll
    for (int i = 0; i < 2; i++) {
        int idx = tid + i * 256;
        if (idx < 384) {
            int row = idx / 6, seg = idx - row * 6;
            cp16(sb + AO_B + (uint32_t)(row * AO_ROWB + seg * 16),
                 g_kvbh + bh*64*HD + row * HD + seg * 8);
        }
    }
    cp_commit();
    cp_wait<0>();
    __syncthreads();

    float acc[2][7][4];
    #pragma unroll
    for (int mt = 0; mt < 2; mt++)
        #pragma unroll
        for (int nt = 0; nt < 7; nt++)
            #pragma unroll
            for (int r = 0; r < 4; r++) acc[mt][nt][r] = 0.f;

    const uint32_t a_base = (uint32_t)((wid*32 + (l & 15)) * AO_ROWB + (l >> 4) * 16);
    const uint32_t b_base = (uint32_t)((((l >> 4) & 1)*8 + (l & 7)) * AO_ROWB
                                       + ((l >> 3) & 1) * 16);

    #pragma unroll
    for (int k = 0; k < 3; k++) {
        const uint32_t ko = k * 32;
        uint32_t bhf[4][4];
        #pragma unroll
        for (int bt = 0; bt < 4; bt++)
            LDSM4(bhf[bt], sb + AO_B + b_base + bt*16*AO_ROWB + ko);
        #pragma unroll
        for (int mt = 0; mt < 2; mt++) {
            uint32_t ah[4];
            LDSM4(ah, sb + a_base + mt*16*AO_ROWB + ko);
            #pragma unroll
            for (int nt = 0; nt < 7; nt++)    // nt 6 = D column (48..55)
                mma16816(acc[mt][nt], ah, &bhf[nt >> 1][(nt & 1)*2]);
        }
    }

    // epilogue: D = col 48 (tile 6 col 0, lanes l&3==0); divide, store fp16
    #pragma unroll
    for (int mt = 0; mt < 2; mt++) {
        float D0 = __shfl_sync(0xFFFFFFFFu, acc[mt][6][0], l & 0x1C);
        float D1 = __shfl_sync(0xFFFFFFFFu, acc[mt][6][2], l & 0x1C);
        float inv0 = 1.f / (D0 + EPS);
        float inv1 = 1.f / (D1 + EPS);
        int r0 = wid*32 + mt*16 + (l >> 2);
        size_t rowbase0 = ((size_t)bh * Nn + n0 + r0) * HD;
        size_t rowbase1 = ((size_t)bh * Nn + n0 + r0 + 8) * HD;
        #pragma unroll
        for (int nt = 0; nt < 6; nt++) {
            int col = nt*8 + (l & 3)*2;
            __half2 h0 = __half2(__float2half(acc[mt][nt][0]*inv0),
                                 __float2half(acc[mt][nt][1]*inv0));
            __half2 h1 = __half2(__float2half(acc[mt][nt][2]*inv1),
                                 __float2half(acc[mt][nt][3]*inv1));
            *(__half2*)&g_athi[rowbase0 + col] = h0;
            *(__half2*)&g_athi[rowbase1 + col] = h1;
        }
    }
}

// ---------------------------------------------------------------------------
extern "C" void kernel_launch(void* const* d_in, const int* in_sizes, int n_in,
                              void* d_out, int out_size)
{
    (void)in_sizes; (void)n_in; (void)out_size;
    const float* x     = (const float*)d_in[0];
    const float* Wqkv  = (const float*)d_in[1];
    const float* Wproj = (const float*)d_in[2];
    const float* bproj = (const float*)d_in[3];
    float* out = (float*)d_out;

    cudaFuncSetAttribute(gemm_mma<0>, cudaFuncAttributeMaxDynamicSharedMemorySize, SMEM_TOTAL);
    cudaFuncSetAttribute(gemm_mma<1>, cudaFuncAttributeMaxDynamicSharedMemorySize, SMEM_TOTAL);
    cudaFuncSetAttribute(kv_agg_mma,  cudaFuncAttributeMaxDynamicSharedMemorySize, SMEM2);
    cudaFuncSetAttribute(attn_out_mma, cudaFuncAttributeMaxDynamicSharedMemorySize, AO_SMEM);

    __half *xh, *wq, *wp, *athi;
    cudaGetSymbolAddress((void**)&xh,   g_xh);
    cudaGetSymbolAddress((void**)&wq,   g_wq);
    cudaGetSymbolAddress((void**)&wp,   g_wp);
    cudaGetSymbolAddress((void**)&athi, g_athi);

    convert_x_kernel<<<(M_ROWS*KDIM/4 + 255)/256, 256>>>(x, M_ROWS*KDIM/4);
    prep_w_kernel<<<(QKV_COLS*KDIM + 255)/256, 256>>>(Wqkv, Wproj);

    gemm_mma<0><<<dim3(M_ROWS/128, QKV_COLS/192), 256, SMEM_TOTAL>>>(
        xh, wq, nullptr, nullptr);

    kv_agg_mma<<<dim3(NBH, SPLITK), 256, SMEM2>>>();
    kvb_conv_kernel<<<NBH, 256>>>();
    attn_out_mma<<<dim3(NBH, Nn/256), 256, AO_SMEM>>>();

    gemm_mma<1><<<dim3(M_ROWS/128, Cc/192), 256, SMEM_TOTAL>>>(
        athi, wp, bproj, out);
}